// round 5
// baseline (speedup 1.0000x reference)
#include <cuda_runtime.h>
#include <cstdint>
#include <math.h>
#include <float.h>

#define B_  8
#define L_  1024
#define D_  512
#define NJ  2047
#define NK  513
#define TOPK 20

// ---------------- scratch ----------------
__device__ float2 g_part[1024 * NK];   // per-block partial spectra
__device__ float2 g_spec[B_ * NK];
__device__ float  g_mean[B_ * NJ];
__device__ float  g_w[B_ * TOPK];
__device__ int    g_shift[TOPK];

__device__ __forceinline__ float2 cmul(float2 a, float2 b) {
    return make_float2(a.x * b.x - a.y * b.y, a.x * b.y + a.y * b.x);
}

// ---------------- FFT kernel ----------------
// grid 1024 blocks (b = blk>>7, 8 rows each), 256 threads.
// Per row: z = q + i*k (features padded 512->1024), 1024-pt radix-4 FFT,
// Hermitian unpack, P = Qf * conj(Kf), accumulate.
__global__ __launch_bounds__(256) void fft_kernel(const float* __restrict__ Q,
                                                  const float* __restrict__ K) {
    __shared__ float  sq[512], sk[512];
    __shared__ float2 z[1024];
    __shared__ float2 tw[1024];
    __shared__ float2 acc[NK];

    const int tid = threadIdx.x;
    const int b   = blockIdx.x >> 7;
    const int l0  = (blockIdx.x & 127) << 3;

    const float W = -6.283185307179586f / 1024.0f;
    for (int i = tid; i < 1024; i += 256) {
        float s, c;
        __sincosf(W * (float)i, &s, &c);
        tw[i] = make_float2(c, s);
    }
    for (int m = tid; m < NK; m += 256) acc[m] = make_float2(0.0f, 0.0f);
    __syncthreads();

    for (int r = 0; r < 8; ++r) {
        const int l = l0 + r;
        const float* qrow = Q + ((size_t)b * L_ + l) * D_;
        const float* krow = K + ((size_t)b * L_ + l) * D_;
        for (int j = tid; j < 512; j += 256) { sq[j] = qrow[j]; sk[j] = krow[j]; }
        __syncthreads();

        // digit-reversed (base-4, 5 digits) load, zero-padded
        #pragma unroll
        for (int ii = 0; ii < 4; ++ii) {
            int i = tid + 256 * ii;
            int d = ((i & 3) << 8) | (((i >> 2) & 3) << 6) | (((i >> 4) & 3) << 4)
                  | (((i >> 6) & 3) << 2) | ((i >> 8) & 3);
            z[i] = (d < 512) ? make_float2(sq[d], sk[d]) : make_float2(0.0f, 0.0f);
        }
        __syncthreads();

        // 5 radix-4 DIT stages, in-place, one butterfly per thread per stage
        #pragma unroll
        for (int s = 0; s < 5; ++s) {
            const int h    = 1 << (2 * s);
            const int rr   = tid & (h - 1);
            const int qq   = tid >> (2 * s);
            const int base = qq * (h << 2) + rr;
            const int e    = rr * (256 >> (2 * s));

            float2 x0 = z[base];
            float2 x1 = cmul(z[base + h],     tw[e]);
            float2 x2 = cmul(z[base + 2 * h], tw[2 * e]);
            float2 x3 = cmul(z[base + 3 * h], tw[3 * e]);

            float2 s02 = make_float2(x0.x + x2.x, x0.y + x2.y);
            float2 d02 = make_float2(x0.x - x2.x, x0.y - x2.y);
            float2 s13 = make_float2(x1.x + x3.x, x1.y + x3.y);
            float2 d13 = make_float2(x1.x - x3.x, x1.y - x3.y);
            // -i*d13 = (d13.y, -d13.x); +i*d13 = (-d13.y, d13.x)
            z[base]         = make_float2(s02.x + s13.x, s02.y + s13.y);
            z[base + h]     = make_float2(d02.x + d13.y, d02.y - d13.x);
            z[base + 2 * h] = make_float2(s02.x - s13.x, s02.y - s13.y);
            z[base + 3 * h] = make_float2(d02.x - d13.y, d02.y + d13.x);
            __syncthreads();
        }

        // Hermitian unpack + multiply-conj accumulate
        for (int m = tid; m < NK; m += 256) {
            float2 Zm = z[m];
            float2 Zr = z[(1024 - m) & 1023];
            float qx = 0.5f * (Zm.x + Zr.x);
            float qy = 0.5f * (Zm.y - Zr.y);
            float kx = 0.5f * (Zm.y + Zr.y);
            float ky = -0.5f * (Zm.x - Zr.x);
            acc[m].x += qx * kx + qy * ky;
            acc[m].y += qy * kx - qx * ky;
        }
        __syncthreads();
    }

    float2* part = g_part + (size_t)blockIdx.x * NK;
    for (int m = tid; m < NK; m += 256) part[m] = acc[m];
}

// ---------------- reduce partials: spec[b,k] = (1/1024) sum_{j<128} part[b*128+j][k] ----------------
__global__ __launch_bounds__(256) void specreduce_kernel() {
    int gw   = blockIdx.x * 8 + (threadIdx.x >> 5);
    int lane = threadIdx.x & 31;
    int b = gw & 7;
    int k = gw >> 3;
    float sx = 0.0f, sy = 0.0f;
    #pragma unroll
    for (int i = 0; i < 4; ++i) {
        float2 p = g_part[(size_t)(b * 128 + lane + 32 * i) * NK + k];
        sx += p.x; sy += p.y;
    }
    #pragma unroll
    for (int o = 16; o > 0; o >>= 1) {
        sx += __shfl_xor_sync(0xffffffffu, sx, o);
        sy += __shfl_xor_sync(0xffffffffu, sy, o);
    }
    if (lane == 0) g_spec[b * NK + k] = make_float2(sx * (1.0f / 1024.0f), sy * (1.0f / 1024.0f));
}

// ---------------- interpolation: one warp per (b,j) ----------------
__global__ __launch_bounds__(256) void meanval_kernel() {
    int gw   = blockIdx.x * 8 + (threadIdx.x >> 5);
    int lane = threadIdx.x & 31;
    int b = gw & 7;
    int j = gw >> 3;
    const float2* sp = g_spec + b * NK;
    const float W = 6.283185307179586f / 2047.0f;
    int idx  = ((lane + 1) * j) % NJ;
    int step = (32 * j) % NJ;
    float acc = 0.0f;
    #pragma unroll
    for (int i = 0; i < 16; ++i) {
        int k = 1 + lane + 32 * i;
        float2 s = sp[k];
        float sn, cs;
        __sincosf(W * (float)idx, &sn, &cs);
        acc += s.x * cs - s.y * sn;
        idx += step; if (idx >= NJ) idx -= NJ;
    }
    acc *= 2.0f;
    #pragma unroll
    for (int o = 16; o > 0; o >>= 1) acc += __shfl_xor_sync(0xffffffffu, acc, o);
    if (lane == 0) g_mean[b * NJ + j] = (acc + sp[0].x) * (1.0f / (float)NJ);
}

// ---------------- top-20 + softmax (warp-shuffle reductions) ----------------
__global__ __launch_bounds__(256) void topk_kernel() {
    int b = blockIdx.x;
    int tid = threadIdx.x;
    int lane = tid & 31;
    int warp = tid >> 5;
    __shared__ float sv[NJ];
    __shared__ float wv[8];
    __shared__ int   wi[8];
    __shared__ float topv[TOPK];
    __shared__ int   topi[TOPK];
    for (int i = tid; i < NJ; i += 256) sv[i] = g_mean[b * NJ + i];
    __syncthreads();
    for (int r = 0; r < TOPK; ++r) {
        float best = -FLT_MAX; int bi = NJ;
        for (int i = tid; i < NJ; i += 256) {
            float v = sv[i];
            if (v > best || (v == best && i < bi)) { best = v; bi = i; }
        }
        #pragma unroll
        for (int o = 16; o > 0; o >>= 1) {
            float v2 = __shfl_xor_sync(0xffffffffu, best, o);
            int   i2 = __shfl_xor_sync(0xffffffffu, bi, o);
            if (v2 > best || (v2 == best && i2 < bi)) { best = v2; bi = i2; }
        }
        if (lane == 0) { wv[warp] = best; wi[warp] = bi; }
        __syncthreads();
        if (warp == 0) {
            float v = (lane < 8) ? wv[lane] : -FLT_MAX;
            int   i = (lane < 8) ? wi[lane] : NJ;
            #pragma unroll
            for (int o = 4; o > 0; o >>= 1) {
                float v2 = __shfl_xor_sync(0xffffffffu, v, o);
                int   i2 = __shfl_xor_sync(0xffffffffu, i, o);
                if (v2 > v || (v2 == v && i2 < i)) { v = v2; i = i2; }
            }
            if (lane == 0) {
                topv[r] = v; topi[r] = i;
                sv[i] = -FLT_MAX;
            }
        }
        __syncthreads();
    }
    if (tid == 0) {
        float mx = topv[0];
        float e[TOPK]; float s = 0.0f;
        for (int k = 0; k < TOPK; ++k) { e[k] = expf(topv[k] - mx); s += e[k]; }
        float inv = 1.0f / s;
        for (int k = 0; k < TOPK; ++k) g_w[b * TOPK + k] = e[k] * inv;
        if (b == 0) for (int k = 0; k < TOPK; ++k) g_shift[k] = topi[k];
    }
}

// ---------------- gather: out[b,l,d] = sum_k w[b,k] * V[b,(l+shift[k])&1023,d] ----------------
__global__ __launch_bounds__(256) void gather_kernel(const float* __restrict__ V,
                                                     float* __restrict__ out) {
    int b  = blockIdx.y;
    int d0 = blockIdx.x * 8;
    __shared__ float sv[L_ * 8];
    __shared__ float sw[TOPK];
    __shared__ int   ssh[TOPK];
    const float* Vb = V + (size_t)b * L_ * D_;
    for (int idx = threadIdx.x; idx < L_ * 8; idx += 256) {
        int row = idx >> 3, c = idx & 7;
        sv[idx] = Vb[(size_t)row * D_ + d0 + c];
    }
    if (threadIdx.x < TOPK) {
        sw[threadIdx.x]  = g_w[b * TOPK + threadIdx.x];
        ssh[threadIdx.x] = g_shift[threadIdx.x] & (L_ - 1);
    }
    __syncthreads();
    int d  = threadIdx.x & 7;
    int lb = threadIdx.x >> 3;
    float* ob = out + (size_t)b * L_ * D_ + d0 + d;
    for (int l = lb; l < L_; l += 32) {
        float acc = 0.0f;
        #pragma unroll
        for (int k = 0; k < TOPK; ++k) {
            int row = (l + ssh[k]) & (L_ - 1);
            acc = fmaf(sw[k], sv[(row << 3) + d], acc);
        }
        ob[(size_t)l * D_] = acc;
    }
}

// ---------------- launch ----------------
extern "C" void kernel_launch(void* const* d_in, const int* in_sizes, int n_in,
                              void* d_out, int out_size) {
    const float* q = (const float*)d_in[0];
    const float* k = (const float*)d_in[1];
    const float* v = (const float*)d_in[2];
    float* out = (float*)d_out;

    fft_kernel<<<1024, 256>>>(q, k);
    specreduce_kernel<<<513, 256>>>();
    meanval_kernel<<<NJ, 256>>>();
    topk_kernel<<<B_, 256>>>();
    gather_kernel<<<dim3(D_ / 8, B_), 256>>>(v, out);
}

// round 6
// speedup vs baseline: 1.3185x; 1.3185x over previous
#include <cuda_runtime.h>
#include <cuda_bf16.h>
#include <cstdint>
#include <math.h>
#include <float.h>

#define B_  8
#define L_  1024
#define D_  512
#define NJ  2047
#define NK  513
#define TOPK 20

#define PADB  24               // bf16 per smem tile row (16 data + 8 pad)
#define TILE_B (128*PADB*2)    // 6144 bytes per operand tile
#define STAGE_B (4*TILE_B)     // 24576 bytes per pipeline stage (Ahi,Alo,Bhi,Blo)
#define CS 130                 // C staging stride (floats)
#define GEMM_SMEM (3*STAGE_B)  // 73728 >= 128*130*4 = 66560 epilogue

// ---------------- scratch ----------------
__device__ float  g_cbar[B_ * L_];
__device__ float2 g_spec[B_ * NK];
__device__ float  g_mean[B_ * NJ];
__device__ float  g_w[B_ * TOPK];
__device__ int    g_shift[TOPK];
__device__ __nv_bfloat16 g_Qt_hi[B_ * D_ * L_];
__device__ __nv_bfloat16 g_Qt_lo[B_ * D_ * L_];
__device__ __nv_bfloat16 g_Kt_hi[B_ * D_ * L_];
__device__ __nv_bfloat16 g_Kt_lo[B_ * D_ * L_];

__global__ void init_kernel() {
    int i = blockIdx.x * blockDim.x + threadIdx.x;
    if (i < B_ * L_) g_cbar[i] = 0.0f;
}

// ---------------- convert+transpose: f32 [b][l][d] -> bf16 hi/lo [b][d][l] ----------------
__global__ __launch_bounds__(256) void convert_kernel(const float* __restrict__ Q,
                                                      const float* __restrict__ K) {
    __shared__ float tile[32][33];
    int which = blockIdx.z >> 3;
    int b     = blockIdx.z & 7;
    const float* src = (which ? K : Q) + (size_t)b * L_ * D_;
    __nv_bfloat16* hi = (which ? g_Kt_hi : g_Qt_hi) + (size_t)b * D_ * L_;
    __nv_bfloat16* lo = (which ? g_Kt_lo : g_Qt_lo) + (size_t)b * D_ * L_;
    int l0 = blockIdx.x * 32, d0 = blockIdx.y * 32;
    #pragma unroll
    for (int i = 0; i < 4; ++i)
        tile[threadIdx.y + 8 * i][threadIdx.x] =
            src[(size_t)(l0 + threadIdx.y + 8 * i) * D_ + d0 + threadIdx.x];
    __syncthreads();
    #pragma unroll
    for (int i = 0; i < 4; ++i) {
        float v = tile[threadIdx.x][threadIdx.y + 8 * i];
        int d = d0 + threadIdx.y + 8 * i;
        int l = l0 + threadIdx.x;
        __nv_bfloat16 h = __float2bfloat16(v);
        hi[(size_t)d * L_ + l] = h;
        lo[(size_t)d * L_ + l] = __float2bfloat16(v - __bfloat162float(h));
    }
}

// ---------------- tensor-core GEMM (cp.async 3-stage) + fused diagonal epilogue ----------------
#define LDSM4(R0, R1, R2, R3, A) \
    asm volatile("ldmatrix.sync.aligned.m8n8.x4.shared.b16 {%0,%1,%2,%3}, [%4];" \
                 : "=r"(R0), "=r"(R1), "=r"(R2), "=r"(R3) : "r"(A))

#define MMA16816(D, A0, A1, A2, A3, B0, B1) \
    asm volatile("mma.sync.aligned.m16n8k16.row.col.f32.bf16.bf16.f32 " \
                 "{%0,%1,%2,%3},{%4,%5,%6,%7},{%8,%9},{%0,%1,%2,%3};" \
                 : "+f"(D[0]), "+f"(D[1]), "+f"(D[2]), "+f"(D[3]) \
                 : "r"(A0), "r"(A1), "r"(A2), "r"(A3), "r"(B0), "r"(B1))

#define CP16(dst, src) \
    asm volatile("cp.async.cg.shared.global [%0], [%1], 16;" :: "r"(dst), "l"(src))
#define CP_COMMIT() asm volatile("cp.async.commit_group;")
#define CP_WAIT1()  asm volatile("cp.async.wait_group 1;")
#define CP_WAIT0()  asm volatile("cp.async.wait_group 0;")

__global__ __launch_bounds__(256, 1) void gemm_kernel() {
    extern __shared__ char sm[];
    const uint32_t smem_base = (uint32_t)__cvta_generic_to_shared(sm);

    const int b  = blockIdx.z;
    const int t0 = blockIdx.y * 128;
    const int u0 = blockIdx.x * 128;
    const __nv_bfloat16* Ahi = g_Qt_hi + (size_t)b * D_ * L_;
    const __nv_bfloat16* Alo = g_Qt_lo + (size_t)b * D_ * L_;
    const __nv_bfloat16* Bhi = g_Kt_hi + (size_t)b * D_ * L_;
    const __nv_bfloat16* Blo = g_Kt_lo + (size_t)b * D_ * L_;

    const int tid  = threadIdx.x;
    const int lane = tid & 31;
    const int warp = tid >> 5;
    const int wm   = warp & 1;
    const int wn   = warp >> 1;

    const int lr = tid >> 1;
    const int lh = tid & 1;
    const size_t a_go = (size_t)(t0 + lr) * L_ + lh * 8;
    const size_t b_go = (size_t)(u0 + lr) * L_ + lh * 8;
    const uint32_t s_byte = (lr * PADB + lh * 8) * 2;

    const int a_row = lane & 15;
    const int a_col = ((lane >> 4) & 1) * 8;
    const int b_row = ((lane >> 4) << 3) + (lane & 7);
    const int b_col = ((lane >> 3) & 1) * 8;

    float acc[4][4][4];
    #pragma unroll
    for (int i = 0; i < 4; ++i)
        #pragma unroll
        for (int j = 0; j < 4; ++j)
            #pragma unroll
            for (int k = 0; k < 4; ++k) acc[i][j][k] = 0.0f;

    // prologue: issue stages 0 and 1
    #pragma unroll
    for (int s = 0; s < 2; ++s) {
        uint32_t dst = smem_base + s * STAGE_B + s_byte;
        size_t off = (size_t)s * 16;
        CP16(dst + 0 * TILE_B, &Ahi[a_go + off]);
        CP16(dst + 1 * TILE_B, &Alo[a_go + off]);
        CP16(dst + 2 * TILE_B, &Bhi[b_go + off]);
        CP16(dst + 3 * TILE_B, &Blo[b_go + off]);
        CP_COMMIT();
    }

    int stage = 0;
    for (int kt = 0; kt < 64; ++kt) {
        if (kt < 63) CP_WAIT1(); else CP_WAIT0();
        __syncthreads();

        const uint32_t base = smem_base + stage * STAGE_B;
        uint32_t ah[4][4], al[4][4], bh[2][4], bl[2][4];
        #pragma unroll
        for (int mt = 0; mt < 4; ++mt) {
            uint32_t addr = base + ((wm * 64 + mt * 16 + a_row) * PADB + a_col) * 2;
            LDSM4(ah[mt][0], ah[mt][1], ah[mt][2], ah[mt][3], addr);
            LDSM4(al[mt][0], al[mt][1], al[mt][2], al[mt][3], addr + TILE_B);
        }
        #pragma unroll
        for (int ng = 0; ng < 2; ++ng) {
            uint32_t addr = base + 2 * TILE_B + ((wn * 32 + ng * 16 + b_row) * PADB + b_col) * 2;
            LDSM4(bh[ng][0], bh[ng][1], bh[ng][2], bh[ng][3], addr);
            LDSM4(bl[ng][0], bl[ng][1], bl[ng][2], bl[ng][3], addr + TILE_B);
        }
        #pragma unroll
        for (int mt = 0; mt < 4; ++mt)
            #pragma unroll
            for (int nt = 0; nt < 4; ++nt) {
                int g = nt >> 1, h = (nt & 1) * 2;
                MMA16816(acc[mt][nt], ah[mt][0], ah[mt][1], ah[mt][2], ah[mt][3],
                         bh[g][h], bh[g][h + 1]);
                MMA16816(acc[mt][nt], al[mt][0], al[mt][1], al[mt][2], al[mt][3],
                         bh[g][h], bh[g][h + 1]);
                MMA16816(acc[mt][nt], ah[mt][0], ah[mt][1], ah[mt][2], ah[mt][3],
                         bl[g][h], bl[g][h + 1]);
            }

        if (kt + 2 < 64) {
            int ns = stage;                 // stage (kt+2)%3 == (stage+2)%3; compute below
            ns = stage + 2; if (ns >= 3) ns -= 3;
            uint32_t dst = smem_base + ns * STAGE_B + s_byte;
            size_t off = (size_t)(kt + 2) * 16;
            CP16(dst + 0 * TILE_B, &Ahi[a_go + off]);
            CP16(dst + 1 * TILE_B, &Alo[a_go + off]);
            CP16(dst + 2 * TILE_B, &Bhi[b_go + off]);
            CP16(dst + 3 * TILE_B, &Blo[b_go + off]);
            CP_COMMIT();
        }
        if (++stage == 3) stage = 0;
    }

    // epilogue: stage C in smem, reduce diagonals
    __syncthreads();
    float* Cs = (float*)sm;
    const int cg = lane >> 2, ct = (lane & 3) * 2;
    #pragma unroll
    for (int mt = 0; mt < 4; ++mt)
        #pragma unroll
        for (int nt = 0; nt < 4; ++nt) {
            int m = wm * 64 + mt * 16 + cg;
            int n = wn * 32 + nt * 8 + ct;
            Cs[m * CS + n]           = acc[mt][nt][0];
            Cs[m * CS + n + 1]       = acc[mt][nt][1];
            Cs[(m + 8) * CS + n]     = acc[mt][nt][2];
            Cs[(m + 8) * CS + n + 1] = acc[mt][nt][3];
        }
    __syncthreads();
    if (tid < 255) {
        int dlt = tid - 127;
        int rlo = dlt > 0 ? dlt : 0;
        int rhi = dlt < 0 ? 127 + dlt : 127;
        float s = 0.0f;
        for (int r = rlo; r <= rhi; ++r) s += Cs[r * CS + (r - dlt)];
        int mi = (t0 - u0 + dlt) & 1023;
        atomicAdd(&g_cbar[b * L_ + mi], s * (1.0f / (float)L_));
    }
}

// ---------------- spectrum: one warp per (b,k) ----------------
__global__ __launch_bounds__(256) void spec_kernel() {
    int gw   = blockIdx.x * 8 + (threadIdx.x >> 5);
    int lane = threadIdx.x & 31;
    int b = gw & 7;
    int k = gw >> 3;
    const float* cb = g_cbar + b * L_;
    const float W = -6.283185307179586f / 1024.0f;
    float re = 0.0f, im = 0.0f;
    int idx  = (k * lane) & 1023;
    int step = (k * 32) & 1023;
    int m = lane;
    #pragma unroll 8
    for (int i = 0; i < 32; ++i) {
        float c = cb[m];
        float sn, cs;
        __sincosf(W * (float)idx, &sn, &cs);
        re = fmaf(c, cs, re);
        im = fmaf(c, sn, im);
        m += 32;
        idx = (idx + step) & 1023;
    }
    #pragma unroll
    for (int o = 16; o > 0; o >>= 1) {
        re += __shfl_xor_sync(0xffffffffu, re, o);
        im += __shfl_xor_sync(0xffffffffu, im, o);
    }
    if (lane == 0) g_spec[b * NK + k] = make_float2(re, im);
}

// ---------------- interpolation: one warp per (b,j) ----------------
__global__ __launch_bounds__(256) void meanval_kernel() {
    int gw   = blockIdx.x * 8 + (threadIdx.x >> 5);
    int lane = threadIdx.x & 31;
    int b = gw & 7;
    int j = gw >> 3;
    const float2* sp = g_spec + b * NK;
    const float W = 6.283185307179586f / 2047.0f;
    int idx  = ((lane + 1) * j) % NJ;
    int step = (32 * j) % NJ;
    float acc = 0.0f;
    #pragma unroll
    for (int i = 0; i < 16; ++i) {
        int k = 1 + lane + 32 * i;
        float2 s = sp[k];
        float sn, cs;
        __sincosf(W * (float)idx, &sn, &cs);
        acc += s.x * cs - s.y * sn;
        idx += step; if (idx >= NJ) idx -= NJ;
    }
    acc *= 2.0f;
    #pragma unroll
    for (int o = 16; o > 0; o >>= 1) acc += __shfl_xor_sync(0xffffffffu, acc, o);
    if (lane == 0) g_mean[b * NJ + j] = (acc + sp[0].x) * (1.0f / (float)NJ);
}

// ---------------- top-20: per-warp local top-20, then warp-0 merge ----------------
__global__ __launch_bounds__(256) void topk_kernel() {
    int b = blockIdx.x;
    int tid = threadIdx.x;
    int lane = tid & 31;
    int warp = tid >> 5;
    __shared__ float cv[8 * TOPK];
    __shared__ int   ci[8 * TOPK];

    // each warp owns 256 indices: i = warp*256 + j*32 + lane
    float v[8]; int gi[8];
    #pragma unroll
    for (int j = 0; j < 8; ++j) {
        int i = warp * 256 + j * 32 + lane;
        gi[j] = i;
        v[j] = (i < NJ) ? g_mean[b * NJ + i] : -FLT_MAX;
    }
    for (int r = 0; r < TOPK; ++r) {
        float best = -FLT_MAX; int bi = NJ;
        #pragma unroll
        for (int j = 0; j < 8; ++j)
            if (v[j] > best || (v[j] == best && gi[j] < bi)) { best = v[j]; bi = gi[j]; }
        #pragma unroll
        for (int o = 16; o > 0; o >>= 1) {
            float v2 = __shfl_xor_sync(0xffffffffu, best, o);
            int   i2 = __shfl_xor_sync(0xffffffffu, bi, o);
            if (v2 > best || (v2 == best && i2 < bi)) { best = v2; bi = i2; }
        }
        // invalidate winner
        if ((bi & 31) == lane) {
            int j = (bi >> 5) & 7;
            if (gi[j] == bi) v[j] = -FLT_MAX;
        }
        if (lane == 0) { cv[warp * TOPK + r] = best; ci[warp * TOPK + r] = bi; }
    }
    __syncthreads();

    if (warp == 0) {
        // merge 160 candidates: 5 per lane
        float mv[5]; int mi[5];
        #pragma unroll
        for (int j = 0; j < 5; ++j) { mv[j] = cv[j * 32 + lane]; mi[j] = ci[j * 32 + lane]; }
        float topv[TOPK]; int topi[TOPK];
        for (int r = 0; r < TOPK; ++r) {
            float best = -FLT_MAX; int bi = NJ; int bj = -1;
            #pragma unroll
            for (int j = 0; j < 5; ++j)
                if (mv[j] > best || (mv[j] == best && mi[j] < bi)) { best = mv[j]; bi = mi[j]; bj = j; }
            #pragma unroll
            for (int o = 16; o > 0; o >>= 1) {
                float v2 = __shfl_xor_sync(0xffffffffu, best, o);
                int   i2 = __shfl_xor_sync(0xffffffffu, bi, o);
                if (v2 > best || (v2 == best && i2 < bi)) { best = v2; bi = i2; bj = -1; }
            }
            // re-derive owner: lane whose candidate matches (best,bi) clears it
            #pragma unroll
            for (int j = 0; j < 5; ++j)
                if (mv[j] == best && mi[j] == bi) mv[j] = -FLT_MAX;
            topv[r] = best; topi[r] = bi;
        }
        if (lane == 0) {
            float mx = topv[0];
            float e[TOPK]; float s = 0.0f;
            for (int k = 0; k < TOPK; ++k) { e[k] = expf(topv[k] - mx); s += e[k]; }
            float inv = 1.0f / s;
            for (int k = 0; k < TOPK; ++k) g_w[b * TOPK + k] = e[k] * inv;
            if (b == 0) for (int k = 0; k < TOPK; ++k) g_shift[k] = topi[k];
        }
    }
}

// ---------------- gather: out[b,l,d] = sum_k w[b,k] * V[b,(l+shift[k])&1023,d] ----------------
__global__ __launch_bounds__(256) void gather_kernel(const float* __restrict__ V,
                                                     float* __restrict__ out) {
    int b  = blockIdx.y;
    int d0 = blockIdx.x * 8;
    __shared__ float sv[L_ * 8];
    __shared__ float sw[TOPK];
    __shared__ int   ssh[TOPK];
    const float* Vb = V + (size_t)b * L_ * D_;
    for (int idx = threadIdx.x; idx < L_ * 8; idx += 256) {
        int row = idx >> 3, c = idx & 7;
        sv[idx] = Vb[(size_t)row * D_ + d0 + c];
    }
    if (threadIdx.x < TOPK) {
        sw[threadIdx.x]  = g_w[b * TOPK + threadIdx.x];
        ssh[threadIdx.x] = g_shift[threadIdx.x] & (L_ - 1);
    }
    __syncthreads();
    int d  = threadIdx.x & 7;
    int lb = threadIdx.x >> 3;
    float* ob = out + (size_t)b * L_ * D_ + d0 + d;
    for (int l = lb; l < L_; l += 32) {
        float acc = 0.0f;
        #pragma unroll
        for (int k = 0; k < TOPK; ++k) {
            int row = (l + ssh[k]) & (L_ - 1);
            acc = fmaf(sw[k], sv[(row << 3) + d], acc);
        }
        ob[(size_t)l * D_] = acc;
    }
}

// ---------------- launch ----------------
extern "C" void kernel_launch(void* const* d_in, const int* in_sizes, int n_in,
                              void* d_out, int out_size) {
    const float* q = (const float*)d_in[0];
    const float* k = (const float*)d_in[1];
    const float* v = (const float*)d_in[2];
    float* out = (float*)d_out;

    cudaFuncSetAttribute(gemm_kernel, cudaFuncAttributeMaxDynamicSharedMemorySize, GEMM_SMEM);

    init_kernel<<<32, 256>>>();
    convert_kernel<<<dim3(32, 16, 16), dim3(32, 8)>>>(q, k);
    gemm_kernel<<<dim3(4, 4, B_), 256, GEMM_SMEM>>>();
    spec_kernel<<<513, 256>>>();
    meanval_kernel<<<NJ, 256>>>();
    topk_kernel<<<B_, 256>>>();
    gather_kernel<<<dim3(D_ / 8, B_), 256>>>(v, out);
}

// round 8
// speedup vs baseline: 1.3762x; 1.0438x over previous
#include <cuda_runtime.h>
#include <cuda_bf16.h>
#include <cstdint>
#include <math.h>
#include <float.h>

#define B_  8
#define L_  1024
#define D_  512
#define NJ  2047
#define NK  513
#define TOPK 20

#define PADB  24               // bf16 per smem tile row (16 data + 8 pad)
#define TILE_B (128*PADB*2)    // 6144 bytes per operand tile
#define STAGE_B (4*TILE_B)     // 24576 per stage (Ahi,Alo,Bhi,Blo)
#define CS 130                 // C staging stride (floats)
#define GEMM_SMEM 66560        // max(2*STAGE_B=49152, 128*130*4=66560)
#define NTHR 320               // 8 MMA warps + 2 producer warps

// ---------------- scratch ----------------
__device__ float  g_cbar[B_ * L_];
__device__ float2 g_spec[B_ * NK];
__device__ float  g_mean[B_ * NJ];
__device__ float  g_w[B_ * TOPK];
__device__ int    g_shift[TOPK];

__global__ void init_kernel() {
    int i = blockIdx.x * blockDim.x + threadIdx.x;
    if (i < B_ * L_) g_cbar[i] = 0.0f;
}

// ---------------- mma helpers ----------------
#define LDSM4(R0, R1, R2, R3, A) \
    asm volatile("ldmatrix.sync.aligned.m8n8.x4.shared.b16 {%0,%1,%2,%3}, [%4];" \
                 : "=r"(R0), "=r"(R1), "=r"(R2), "=r"(R3) : "r"(A))

#define MMA16816(D, A0, A1, A2, A3, B0, B1) \
    asm volatile("mma.sync.aligned.m16n8k16.row.col.f32.bf16.bf16.f32 " \
                 "{%0,%1,%2,%3},{%4,%5,%6,%7},{%8,%9},{%0,%1,%2,%3};" \
                 : "+f"(D[0]), "+f"(D[1]), "+f"(D[2]), "+f"(D[3]) \
                 : "r"(A0), "r"(A1), "r"(A2), "r"(A3), "r"(B0), "r"(B1))

__device__ __forceinline__ uint32_t pack_bf16(float a, float b) {
    __nv_bfloat162 h = __floats2bfloat162_rn(a, b);
    return *(uint32_t*)&h;
}

// ---------------- fused convert + tensor-core GEMM + diagonal epilogue ----------------
// grid (4,4,8), block 320. Warps 0-7: MMA consumers. Warps 8-9: gmem->bf16 hi/lo producers.
__global__ __launch_bounds__(NTHR, 1) void gemm_kernel(const float* __restrict__ Q,
                                                       const float* __restrict__ K) {
    extern __shared__ __align__(128) char sm[];
    const uint32_t smem_base = (uint32_t)__cvta_generic_to_shared(sm);

    const int b  = blockIdx.z;
    const int t0 = blockIdx.y * 128;
    const int u0 = blockIdx.x * 128;
    const float* Qb = Q + (size_t)b * L_ * D_;
    const float* Kb = K + (size_t)b * L_ * D_;

    const int tid  = threadIdx.x;
    const int lane = tid & 31;
    const int warp = tid >> 5;

    if (warp >= 8) {
        // ---------------- producer ----------------
        const int tl = (warp - 8) * 32 + lane;   // 0..63, handles t = tl and tl+64
        // prologue: fill stage 0 (kt = 0), then one stage ahead each iteration.
        for (int fill = 0; fill < 65; ++fill) {
            if (fill < 64) {
                const int kt = fill;
                char* stg = sm + (kt & 1) * STAGE_B;
                float v[2][2][16];
                #pragma unroll
                for (int op = 0; op < 2; ++op) {
                    const float* src = (op ? Kb : Qb) + (size_t)(kt * 16) * D_
                                     + (op ? u0 : t0) + tl;
                    #pragma unroll
                    for (int h = 0; h < 2; ++h)
                        #pragma unroll
                        for (int l = 0; l < 16; ++l)
                            v[op][h][l] = src[(size_t)l * D_ + h * 64];
                }
                #pragma unroll
                for (int op = 0; op < 2; ++op) {
                    #pragma unroll
                    for (int h = 0; h < 2; ++h) {
                        int t = tl + h * 64;
                        uint32_t hi[8], lo[8];
                        #pragma unroll
                        for (int i = 0; i < 8; ++i) {
                            float a = v[op][h][2 * i], c = v[op][h][2 * i + 1];
                            __nv_bfloat16 ha = __float2bfloat16(a);
                            __nv_bfloat16 hc = __float2bfloat16(c);
                            hi[i] = ((uint32_t)*(uint16_t*)&hc << 16) | *(uint16_t*)&ha;
                            lo[i] = pack_bf16(a - __bfloat162float(ha),
                                              c - __bfloat162float(hc));
                        }
                        char* dhi = stg + op * 2 * TILE_B + t * (PADB * 2);
                        char* dlo = dhi + TILE_B;
                        ((uint4*)dhi)[0] = make_uint4(hi[0], hi[1], hi[2], hi[3]);
                        ((uint4*)dhi)[1] = make_uint4(hi[4], hi[5], hi[6], hi[7]);
                        ((uint4*)dlo)[0] = make_uint4(lo[0], lo[1], lo[2], lo[3]);
                        ((uint4*)dlo)[1] = make_uint4(lo[4], lo[5], lo[6], lo[7]);
                    }
                }
            }
            __syncthreads();
        }
    } else {
        // ---------------- consumer ----------------
        const int wm = warp & 1;
        const int wn = warp >> 1;
        const int a_row = lane & 15;
        const int a_col = ((lane >> 4) & 1) * 8;
        const int b_row = ((lane >> 4) << 3) + (lane & 7);
        const int b_col = ((lane >> 3) & 1) * 8;

        float acc[4][4][4];
        #pragma unroll
        for (int i = 0; i < 4; ++i)
            #pragma unroll
            for (int j = 0; j < 4; ++j)
                #pragma unroll
                for (int k = 0; k < 4; ++k) acc[i][j][k] = 0.0f;

        __syncthreads();   // match producer prologue sync (stage 0 ready)

        for (int kt = 0; kt < 64; ++kt) {
            const uint32_t base = smem_base + (kt & 1) * STAGE_B;
            uint32_t ah[4][4], al[4][4], bh[2][4], bl[2][4];
            #pragma unroll
            for (int mt = 0; mt < 4; ++mt) {
                uint32_t addr = base + ((wm * 64 + mt * 16 + a_row) * PADB + a_col) * 2;
                LDSM4(ah[mt][0], ah[mt][1], ah[mt][2], ah[mt][3], addr);
                LDSM4(al[mt][0], al[mt][1], al[mt][2], al[mt][3], addr + TILE_B);
            }
            #pragma unroll
            for (int ng = 0; ng < 2; ++ng) {
                uint32_t addr = base + 2 * TILE_B
                              + ((wn * 32 + ng * 16 + b_row) * PADB + b_col) * 2;
                LDSM4(bh[ng][0], bh[ng][1], bh[ng][2], bh[ng][3], addr);
                LDSM4(bl[ng][0], bl[ng][1], bl[ng][2], bl[ng][3], addr + TILE_B);
            }
            #pragma unroll
            for (int mt = 0; mt < 4; ++mt)
                #pragma unroll
                for (int nt = 0; nt < 4; ++nt) {
                    int g = nt >> 1, h = (nt & 1) * 2;
                    MMA16816(acc[mt][nt], ah[mt][0], ah[mt][1], ah[mt][2], ah[mt][3],
                             bh[g][h], bh[g][h + 1]);
                    MMA16816(acc[mt][nt], al[mt][0], al[mt][1], al[mt][2], al[mt][3],
                             bh[g][h], bh[g][h + 1]);
                    MMA16816(acc[mt][nt], ah[mt][0], ah[mt][1], ah[mt][2], ah[mt][3],
                             bl[g][h], bl[g][h + 1]);
                }
            __syncthreads();
        }

        // stage C in smem
        float* Cs = (float*)sm;
        const int cg = lane >> 2, ct = (lane & 3) * 2;
        #pragma unroll
        for (int mt = 0; mt < 4; ++mt)
            #pragma unroll
            for (int nt = 0; nt < 4; ++nt) {
                int m = wm * 64 + mt * 16 + cg;
                int n = wn * 32 + nt * 8 + ct;
                Cs[m * CS + n]           = acc[mt][nt][0];
                Cs[m * CS + n + 1]       = acc[mt][nt][1];
                Cs[(m + 8) * CS + n]     = acc[mt][nt][2];
                Cs[(m + 8) * CS + n + 1] = acc[mt][nt][3];
            }
    }
    __syncthreads();

    // diagonal reduce (255 threads)
    const float* Cs = (const float*)sm;
    if (tid < 255) {
        int dlt = tid - 127;
        int rlo = dlt > 0 ? dlt : 0;
        int rhi = dlt < 0 ? 127 + dlt : 127;
        float s = 0.0f;
        for (int rr = rlo; rr <= rhi; ++rr) s += Cs[rr * CS + (rr - dlt)];
        int mi = (t0 - u0 + dlt) & 1023;
        atomicAdd(&g_cbar[b * L_ + mi], s * (1.0f / (float)L_));
    }
}

// ---------------- spectrum: one warp per (b,k) ----------------
__global__ __launch_bounds__(256) void spec_kernel() {
    int gw   = blockIdx.x * 8 + (threadIdx.x >> 5);
    int lane = threadIdx.x & 31;
    int b = gw & 7;
    int k = gw >> 3;
    const float* cb = g_cbar + b * L_;
    const float W = -6.283185307179586f / 1024.0f;
    float re = 0.0f, im = 0.0f;
    int idx  = (k * lane) & 1023;
    int step = (k * 32) & 1023;
    int m = lane;
    #pragma unroll 8
    for (int i = 0; i < 32; ++i) {
        float c = cb[m];
        float sn, cs;
        __sincosf(W * (float)idx, &sn, &cs);
        re = fmaf(c, cs, re);
        im = fmaf(c, sn, im);
        m += 32;
        idx = (idx + step) & 1023;
    }
    #pragma unroll
    for (int o = 16; o > 0; o >>= 1) {
        re += __shfl_xor_sync(0xffffffffu, re, o);
        im += __shfl_xor_sync(0xffffffffu, im, o);
    }
    if (lane == 0) g_spec[b * NK + k] = make_float2(re, im);
}

// ---------------- interpolation: one warp per (b,j) ----------------
__global__ __launch_bounds__(256) void meanval_kernel() {
    int gw   = blockIdx.x * 8 + (threadIdx.x >> 5);
    int lane = threadIdx.x & 31;
    int b = gw & 7;
    int j = gw >> 3;
    const float2* sp = g_spec + b * NK;
    const float W = 6.283185307179586f / 2047.0f;
    int idx  = ((lane + 1) * j) % NJ;
    int step = (32 * j) % NJ;
    float acc = 0.0f;
    #pragma unroll
    for (int i = 0; i < 16; ++i) {
        int k = 1 + lane + 32 * i;
        float2 s = sp[k];
        float sn, cs;
        __sincosf(W * (float)idx, &sn, &cs);
        acc += s.x * cs - s.y * sn;
        idx += step; if (idx >= NJ) idx -= NJ;
    }
    acc *= 2.0f;
    #pragma unroll
    for (int o = 16; o > 0; o >>= 1) acc += __shfl_xor_sync(0xffffffffu, acc, o);
    if (lane == 0) g_mean[b * NJ + j] = (acc + sp[0].x) * (1.0f / (float)NJ);
}

// ---------------- top-20: per-warp local top-20, then warp-0 merge ----------------
__global__ __launch_bounds__(256) void topk_kernel() {
    int b = blockIdx.x;
    int tid = threadIdx.x;
    int lane = tid & 31;
    int warp = tid >> 5;
    __shared__ float cv[8 * TOPK];
    __shared__ int   ci[8 * TOPK];

    float v[8]; int gi[8];
    #pragma unroll
    for (int j = 0; j < 8; ++j) {
        int i = warp * 256 + j * 32 + lane;
        gi[j] = i;
        v[j] = (i < NJ) ? g_mean[b * NJ + i] : -FLT_MAX;
    }
    for (int r = 0; r < TOPK; ++r) {
        float best = -FLT_MAX; int bi = NJ;
        #pragma unroll
        for (int j = 0; j < 8; ++j)
            if (v[j] > best || (v[j] == best && gi[j] < bi)) { best = v[j]; bi = gi[j]; }
        #pragma unroll
        for (int o = 16; o > 0; o >>= 1) {
            float v2 = __shfl_xor_sync(0xffffffffu, best, o);
            int   i2 = __shfl_xor_sync(0xffffffffu, bi, o);
            if (v2 > best || (v2 == best && i2 < bi)) { best = v2; bi = i2; }
        }
        if ((bi & 31) == lane) {
            int j = (bi >> 5) & 7;
            if (gi[j] == bi) v[j] = -FLT_MAX;
        }
        if (lane == 0) { cv[warp * TOPK + r] = best; ci[warp * TOPK + r] = bi; }
    }
    __syncthreads();

    if (warp == 0) {
        float mv[5]; int mi[5];
        #pragma unroll
        for (int j = 0; j < 5; ++j) { mv[j] = cv[j * 32 + lane]; mi[j] = ci[j * 32 + lane]; }
        float topv[TOPK]; int topi[TOPK];
        for (int r = 0; r < TOPK; ++r) {
            float best = -FLT_MAX; int bi = NJ;
            #pragma unroll
            for (int j = 0; j < 5; ++j)
                if (mv[j] > best || (mv[j] == best && mi[j] < bi)) { best = mv[j]; bi = mi[j]; }
            #pragma unroll
            for (int o = 16; o > 0; o >>= 1) {
                float v2 = __shfl_xor_sync(0xffffffffu, best, o);
                int   i2 = __shfl_xor_sync(0xffffffffu, bi, o);
                if (v2 > best || (v2 == best && i2 < bi)) { best = v2; bi = i2; }
            }
            #pragma unroll
            for (int j = 0; j < 5; ++j)
                if (mv[j] == best && mi[j] == bi) mv[j] = -FLT_MAX;
            topv[r] = best; topi[r] = bi;
        }
        if (lane == 0) {
            float mx = topv[0];
            float e[TOPK]; float s = 0.0f;
            for (int k = 0; k < TOPK; ++k) { e[k] = expf(topv[k] - mx); s += e[k]; }
            float inv = 1.0f / s;
            for (int k = 0; k < TOPK; ++k) g_w[b * TOPK + k] = e[k] * inv;
            if (b == 0) for (int k = 0; k < TOPK; ++k) g_shift[k] = topi[k];
        }
    }
}

// ---------------- gather: out[b,l,d] = sum_k w[b,k] * V[b,(l+shift[k])&1023,d] ----------------
__global__ __launch_bounds__(256) void gather_kernel(const float* __restrict__ V,
                                                     float* __restrict__ out) {
    int b  = blockIdx.y;
    int d0 = blockIdx.x * 8;
    __shared__ float sv[L_ * 8];
    __shared__ float sw[TOPK];
    __shared__ int   ssh[TOPK];
    const float* Vb = V + (size_t)b * L_ * D_;
    for (int idx = threadIdx.x; idx < L_ * 8; idx += 256) {
        int row = idx >> 3, c = idx & 7;
        sv[idx] = Vb[(size_t)row * D_ + d0 + c];
    }
    if (threadIdx.x < TOPK) {
        sw[threadIdx.x]  = g_w[b * TOPK + threadIdx.x];
        ssh[threadIdx.x] = g_shift[threadIdx.x] & (L_ - 1);
    }
    __syncthreads();
    int d  = threadIdx.x & 7;
    int lb = threadIdx.x >> 3;
    float* ob = out + (size_t)b * L_ * D_ + d0 + d;
    for (int l = lb; l < L_; l += 32) {
        float acc = 0.0f;
        #pragma unroll
        for (int k = 0; k < TOPK; ++k) {
            int row = (l + ssh[k]) & (L_ - 1);
            acc = fmaf(sw[k], sv[(row << 3) + d], acc);
        }
        ob[(size_t)l * D_] = acc;
    }
}

// ---------------- launch ----------------
extern "C" void kernel_launch(void* const* d_in, const int* in_sizes, int n_in,
                              void* d_out, int out_size) {
    const float* q = (const float*)d_in[0];
    const float* k = (const float*)d_in[1];
    const float* v = (const float*)d_in[2];
    float* out = (float*)d_out;

    cudaFuncSetAttribute(gemm_kernel, cudaFuncAttributeMaxDynamicSharedMemorySize, GEMM_SMEM);

    init_kernel<<<32, 256>>>();
    gemm_kernel<<<dim3(4, 4, B_), NTHR, GEMM_SMEM>>>(q, k);
    spec_kernel<<<513, 256>>>();
    meanval_kernel<<<NJ, 256>>>();
    topk_kernel<<<B_, 256>>>();
    gather_kernel<<<dim3(D_ / 8, B_), 256>>>(v, out);
}

// round 9
// speedup vs baseline: 1.4138x; 1.0273x over previous
#include <cuda_runtime.h>
#include <cuda_bf16.h>
#include <cstdint>
#include <math.h>
#include <float.h>

#define B_  8
#define L_  1024
#define D_  512
#define NJ  2047
#define NK  513
#define TOPK 20

#define PADB  24               // bf16 per smem tile row (16 data + 8 pad)
#define TILE_B (128*PADB*2)    // 6144 bytes per operand tile
#define STAGE_B (4*TILE_B)     // 24576 per stage (Ahi,Alo,Bhi,Blo)
#define CS 130                 // C staging stride (floats)
#define GEMM_SMEM 66560        // max(2*STAGE_B=49152, 128*130*4=66560)
#define NTHR 320               // 8 MMA warps + 2 producer warps

// ---------------- scratch ----------------
__device__ float  g_cbar[B_ * L_];
__device__ float2 g_spec[B_ * NK];
__device__ float  g_mean[B_ * NJ];
__device__ float  g_w[B_ * TOPK];
__device__ int    g_shift[TOPK];

__global__ void init_kernel() {
    int i = blockIdx.x * blockDim.x + threadIdx.x;
    if (i < B_ * L_) g_cbar[i] = 0.0f;
}

// ---------------- mma helpers ----------------
#define LDSM4(R0, R1, R2, R3, A) \
    asm volatile("ldmatrix.sync.aligned.m8n8.x4.shared.b16 {%0,%1,%2,%3}, [%4];" \
                 : "=r"(R0), "=r"(R1), "=r"(R2), "=r"(R3) : "r"(A))

#define MMA16816(D, A0, A1, A2, A3, B0, B1) \
    asm volatile("mma.sync.aligned.m16n8k16.row.col.f32.bf16.bf16.f32 " \
                 "{%0,%1,%2,%3},{%4,%5,%6,%7},{%8,%9},{%0,%1,%2,%3};" \
                 : "+f"(D[0]), "+f"(D[1]), "+f"(D[2]), "+f"(D[3]) \
                 : "r"(A0), "r"(A1), "r"(A2), "r"(A3), "r"(B0), "r"(B1))

__device__ __forceinline__ uint32_t pack_bf16(float a, float b) {
    __nv_bfloat162 h = __floats2bfloat162_rn(a, b);
    return *(uint32_t*)&h;
}

// ---------------- fused convert + tensor-core GEMM + diagonal epilogue ----------------
// grid (4,4,8), block 320. Warps 0-7: MMA consumers. Warps 8-9: gmem->bf16 hi/lo producers.
__global__ __launch_bounds__(NTHR, 1) void gemm_kernel(const float* __restrict__ Q,
                                                       const float* __restrict__ K) {
    extern __shared__ __align__(128) char sm[];
    const uint32_t smem_base = (uint32_t)__cvta_generic_to_shared(sm);

    const int b  = blockIdx.z;
    const int t0 = blockIdx.y * 128;
    const int u0 = blockIdx.x * 128;
    const float* Qb = Q + (size_t)b * L_ * D_;
    const float* Kb = K + (size_t)b * L_ * D_;

    const int tid  = threadIdx.x;
    const int lane = tid & 31;
    const int warp = tid >> 5;

    if (warp >= 8) {
        // ---------------- producer ----------------
        const int tl = (warp - 8) * 32 + lane;   // 0..63, handles t = tl and tl+64
        for (int fill = 0; fill < 65; ++fill) {
            if (fill < 64) {
                const int kt = fill;
                char* stg = sm + (kt & 1) * STAGE_B;
                float v[2][2][16];
                #pragma unroll
                for (int op = 0; op < 2; ++op) {
                    const float* src = (op ? Kb : Qb) + (size_t)(kt * 16) * D_
                                     + (op ? u0 : t0) + tl;
                    #pragma unroll
                    for (int h = 0; h < 2; ++h)
                        #pragma unroll
                        for (int l = 0; l < 16; ++l)
                            v[op][h][l] = src[(size_t)l * D_ + h * 64];
                }
                #pragma unroll
                for (int op = 0; op < 2; ++op) {
                    #pragma unroll
                    for (int h = 0; h < 2; ++h) {
                        int t = tl + h * 64;
                        uint32_t hi[8], lo[8];
                        #pragma unroll
                        for (int i = 0; i < 8; ++i) {
                            float a = v[op][h][2 * i], c = v[op][h][2 * i + 1];
                            __nv_bfloat16 ha = __float2bfloat16(a);
                            __nv_bfloat16 hc = __float2bfloat16(c);
                            hi[i] = ((uint32_t)*(uint16_t*)&hc << 16) | *(uint16_t*)&ha;
                            lo[i] = pack_bf16(a - __bfloat162float(ha),
                                              c - __bfloat162float(hc));
                        }
                        char* dhi = stg + op * 2 * TILE_B + t * (PADB * 2);
                        char* dlo = dhi + TILE_B;
                        ((uint4*)dhi)[0] = make_uint4(hi[0], hi[1], hi[2], hi[3]);
                        ((uint4*)dhi)[1] = make_uint4(hi[4], hi[5], hi[6], hi[7]);
                        ((uint4*)dlo)[0] = make_uint4(lo[0], lo[1], lo[2], lo[3]);
                        ((uint4*)dlo)[1] = make_uint4(lo[4], lo[5], lo[6], lo[7]);
                    }
                }
            }
            __syncthreads();
        }
    } else {
        // ---------------- consumer ----------------
        const int wm = warp & 1;
        const int wn = warp >> 1;
        const int a_row = lane & 15;
        const int a_col = ((lane >> 4) & 1) * 8;
        const int b_row = ((lane >> 4) << 3) + (lane & 7);
        const int b_col = ((lane >> 3) & 1) * 8;

        float acc[4][4][4];
        #pragma unroll
        for (int i = 0; i < 4; ++i)
            #pragma unroll
            for (int j = 0; j < 4; ++j)
                #pragma unroll
                for (int k = 0; k < 4; ++k) acc[i][j][k] = 0.0f;

        __syncthreads();   // stage 0 ready

        for (int kt = 0; kt < 64; ++kt) {
            const uint32_t base = smem_base + (kt & 1) * STAGE_B;
            uint32_t ah[4][4], al[4][4], bh[2][4], bl[2][4];
            #pragma unroll
            for (int mt = 0; mt < 4; ++mt) {
                uint32_t addr = base + ((wm * 64 + mt * 16 + a_row) * PADB + a_col) * 2;
                LDSM4(ah[mt][0], ah[mt][1], ah[mt][2], ah[mt][3], addr);
                LDSM4(al[mt][0], al[mt][1], al[mt][2], al[mt][3], addr + TILE_B);
            }
            #pragma unroll
            for (int ng = 0; ng < 2; ++ng) {
                uint32_t addr = base + 2 * TILE_B
                              + ((wn * 32 + ng * 16 + b_row) * PADB + b_col) * 2;
                LDSM4(bh[ng][0], bh[ng][1], bh[ng][2], bh[ng][3], addr);
                LDSM4(bl[ng][0], bl[ng][1], bl[ng][2], bl[ng][3], addr + TILE_B);
            }
            #pragma unroll
            for (int mt = 0; mt < 4; ++mt)
                #pragma unroll
                for (int nt = 0; nt < 4; ++nt) {
                    int g = nt >> 1, h = (nt & 1) * 2;
                    MMA16816(acc[mt][nt], ah[mt][0], ah[mt][1], ah[mt][2], ah[mt][3],
                             bh[g][h], bh[g][h + 1]);
                    MMA16816(acc[mt][nt], al[mt][0], al[mt][1], al[mt][2], al[mt][3],
                             bh[g][h], bh[g][h + 1]);
                    MMA16816(acc[mt][nt], ah[mt][0], ah[mt][1], ah[mt][2], ah[mt][3],
                             bl[g][h], bl[g][h + 1]);
                }
            __syncthreads();
        }

        // stage C in smem
        float* Cs = (float*)sm;
        const int cg = lane >> 2, ct = (lane & 3) * 2;
        #pragma unroll
        for (int mt = 0; mt < 4; ++mt)
            #pragma unroll
            for (int nt = 0; nt < 4; ++nt) {
                int m = wm * 64 + mt * 16 + cg;
                int n = wn * 32 + nt * 8 + ct;
                Cs[m * CS + n]           = acc[mt][nt][0];
                Cs[m * CS + n + 1]       = acc[mt][nt][1];
                Cs[(m + 8) * CS + n]     = acc[mt][nt][2];
                Cs[(m + 8) * CS + n + 1] = acc[mt][nt][3];
            }
    }
    __syncthreads();

    // diagonal reduce (255 threads)
    const float* Cs = (const float*)sm;
    if (tid < 255) {
        int dlt = tid - 127;
        int rlo = dlt > 0 ? dlt : 0;
        int rhi = dlt < 0 ? 127 + dlt : 127;
        float s = 0.0f;
        for (int rr = rlo; rr <= rhi; ++rr) s += Cs[rr * CS + (rr - dlt)];
        int mi = (t0 - u0 + dlt) & 1023;
        atomicAdd(&g_cbar[b * L_ + mi], s * (1.0f / (float)L_));
    }
}

// ---------------- spectrum: one warp per (b,k), phasor recurrence ----------------
__global__ __launch_bounds__(256) void spec_kernel() {
    int gw   = blockIdx.x * 8 + (threadIdx.x >> 5);
    int lane = threadIdx.x & 31;
    int b = gw & 7;
    int k = gw >> 3;
    const float* cb = g_cbar + b * L_;
    const float W = -6.283185307179586f / 1024.0f;
    float2 w, ws;
    __sincosf(W * (float)((k * lane) & 1023), &w.y, &w.x);
    __sincosf(W * (float)((k * 32) & 1023), &ws.y, &ws.x);
    float re = 0.0f, im = 0.0f;
    int m = lane;
    #pragma unroll 8
    for (int i = 0; i < 32; ++i) {
        float c = cb[m];
        re = fmaf(c, w.x, re);
        im = fmaf(c, w.y, im);
        float wx = w.x * ws.x - w.y * ws.y;
        w.y = w.x * ws.y + w.y * ws.x;
        w.x = wx;
        m += 32;
    }
    #pragma unroll
    for (int o = 16; o > 0; o >>= 1) {
        re += __shfl_xor_sync(0xffffffffu, re, o);
        im += __shfl_xor_sync(0xffffffffu, im, o);
    }
    if (lane == 0) g_spec[b * NK + k] = make_float2(re, im);
}

// ---------------- interpolation: one warp per (b,j), phasor recurrence ----------------
__global__ __launch_bounds__(256) void meanval_kernel() {
    int gw   = blockIdx.x * 8 + (threadIdx.x >> 5);
    int lane = threadIdx.x & 31;
    int b = gw & 7;
    int j = gw >> 3;
    const float2* sp = g_spec + b * NK;
    const float W = 6.283185307179586f / 2047.0f;
    float2 w, ws;
    __sincosf(W * (float)(((lane + 1) * j) % NJ), &w.y, &w.x);
    __sincosf(W * (float)((32 * j) % NJ), &ws.y, &ws.x);
    float acc = 0.0f;
    #pragma unroll
    for (int i = 0; i < 16; ++i) {
        int k = 1 + lane + 32 * i;
        float2 s = sp[k];
        acc += s.x * w.x - s.y * w.y;
        float wx = w.x * ws.x - w.y * ws.y;
        w.y = w.x * ws.y + w.y * ws.x;
        w.x = wx;
    }
    acc *= 2.0f;
    #pragma unroll
    for (int o = 16; o > 0; o >>= 1) acc += __shfl_xor_sync(0xffffffffu, acc, o);
    if (lane == 0) g_mean[b * NJ + j] = (acc + sp[0].x) * (1.0f / (float)NJ);
}

// ---------------- top-20: per-warp local top-20, then warp-0 merge ----------------
__global__ __launch_bounds__(256) void topk_kernel() {
    int b = blockIdx.x;
    int tid = threadIdx.x;
    int lane = tid & 31;
    int warp = tid >> 5;
    __shared__ float cv[8 * TOPK];
    __shared__ int   ci[8 * TOPK];

    float v[8]; int gi[8];
    #pragma unroll
    for (int j = 0; j < 8; ++j) {
        int i = warp * 256 + j * 32 + lane;
        gi[j] = i;
        v[j] = (i < NJ) ? g_mean[b * NJ + i] : -FLT_MAX;
    }
    for (int r = 0; r < TOPK; ++r) {
        float best = -FLT_MAX; int bi = NJ;
        #pragma unroll
        for (int j = 0; j < 8; ++j)
            if (v[j] > best || (v[j] == best && gi[j] < bi)) { best = v[j]; bi = gi[j]; }
        #pragma unroll
        for (int o = 16; o > 0; o >>= 1) {
            float v2 = __shfl_xor_sync(0xffffffffu, best, o);
            int   i2 = __shfl_xor_sync(0xffffffffu, bi, o);
            if (v2 > best || (v2 == best && i2 < bi)) { best = v2; bi = i2; }
        }
        if ((bi & 31) == lane) {
            int j = (bi >> 5) & 7;
            if (gi[j] == bi) v[j] = -FLT_MAX;
        }
        if (lane == 0) { cv[warp * TOPK + r] = best; ci[warp * TOPK + r] = bi; }
    }
    __syncthreads();

    if (warp == 0) {
        float mv[5]; int mi[5];
        #pragma unroll
        for (int j = 0; j < 5; ++j) { mv[j] = cv[j * 32 + lane]; mi[j] = ci[j * 32 + lane]; }
        float topv[TOPK]; int topi[TOPK];
        for (int r = 0; r < TOPK; ++r) {
            float best = -FLT_MAX; int bi = NJ;
            #pragma unroll
            for (int j = 0; j < 5; ++j)
                if (mv[j] > best || (mv[j] == best && mi[j] < bi)) { best = mv[j]; bi = mi[j]; }
            #pragma unroll
            for (int o = 16; o > 0; o >>= 1) {
                float v2 = __shfl_xor_sync(0xffffffffu, best, o);
                int   i2 = __shfl_xor_sync(0xffffffffu, bi, o);
                if (v2 > best || (v2 == best && i2 < bi)) { best = v2; bi = i2; }
            }
            #pragma unroll
            for (int j = 0; j < 5; ++j)
                if (mv[j] == best && mi[j] == bi) mv[j] = -FLT_MAX;
            topv[r] = best; topi[r] = bi;
        }
        if (lane == 0) {
            float mx = topv[0];
            float e[TOPK]; float s = 0.0f;
            for (int k = 0; k < TOPK; ++k) { e[k] = expf(topv[k] - mx); s += e[k]; }
            float inv = 1.0f / s;
            for (int k = 0; k < TOPK; ++k) g_w[b * TOPK + k] = e[k] * inv;
            if (b == 0) for (int k = 0; k < TOPK; ++k) g_shift[k] = topi[k];
        }
    }
}

// ---------------- gather: out[b,l,d] = sum_k w[b,k] * V[b,(l+shift[k])&1023,d] ----------------
__global__ __launch_bounds__(256) void gather_kernel(const float* __restrict__ V,
                                                     float* __restrict__ out) {
    int b  = blockIdx.y;
    int d0 = blockIdx.x * 8;
    __shared__ float sv[L_ * 8];
    __shared__ float sw[TOPK];
    __shared__ int   ssh[TOPK];
    const float* Vb = V + (size_t)b * L_ * D_;
    for (int idx = threadIdx.x; idx < L_ * 8; idx += 256) {
        int row = idx >> 3, c = idx & 7;
        sv[idx] = Vb[(size_t)row * D_ + d0 + c];
    }
    if (threadIdx.x < TOPK) {
        sw[threadIdx.x]  = g_w[b * TOPK + threadIdx.x];
        ssh[threadIdx.x] = g_shift[threadIdx.x] & (L_ - 1);
    }
    __syncthreads();
    int d  = threadIdx.x & 7;
    int lb = threadIdx.x >> 3;
    float* ob = out + (size_t)b * L_ * D_ + d0 + d;
    for (int l = lb; l < L_; l += 32) {
        float acc = 0.0f;
        #pragma unroll
        for (int k = 0; k < TOPK; ++k) {
            int row = (l + ssh[k]) & (L_ - 1);
            acc = fmaf(sw[k], sv[(row << 3) + d], acc);
        }
        ob[(size_t)l * D_] = acc;
    }
}

// ---------------- launch ----------------
extern "C" void kernel_launch(void* const* d_in, const int* in_sizes, int n_in,
                              void* d_out, int out_size) {
    const float* q = (const float*)d_in[0];
    const float* k = (const float*)d_in[1];
    const float* v = (const float*)d_in[2];
    float* out = (float*)d_out;

    cudaFuncSetAttribute(gemm_kernel, cudaFuncAttributeMaxDynamicSharedMemorySize, GEMM_SMEM);

    init_kernel<<<32, 256>>>();
    gemm_kernel<<<dim3(4, 4, B_), NTHR, GEMM_SMEM>>>(q, k);
    spec_kernel<<<513, 256>>>();
    meanval_kernel<<<NJ, 256>>>();
    topk_kernel<<<B_, 256>>>();
    gather_kernel<<<dim3(D_ / 8, B_), 256>>>(v, out);
}

// round 10
// speedup vs baseline: 1.6419x; 1.1614x over previous
#include <cuda_runtime.h>
#include <cuda_fp16.h>
#include <cstdint>
#include <math.h>
#include <float.h>

#define B_  8
#define L_  1024
#define D_  512
#define NJ  2047
#define NK  513
#define TOPK 20

#define PADB  24               // fp16 per smem tile row (16 data + 8 pad)
#define TILE_B (128*PADB*2)    // 6144 bytes per operand tile
#define STAGE_B (3*TILE_B)     // 18432 per stage (Ahi, Alo, Bhi)
#define CS 130                 // C staging stride (floats)
#define GEMM_SMEM 66560        // max(2*STAGE_B=36864, 128*130*4=66560)
#define NTHR 320               // 8 MMA warps + 2 producer warps

// ---------------- scratch ----------------
__device__ float  g_cbar[B_ * L_];
__device__ float2 g_spec[B_ * NK];
__device__ float  g_mean[B_ * NJ];
__device__ float  g_w[B_ * TOPK];
__device__ int    g_shift[TOPK];

__global__ void init_kernel() {
    int i = blockIdx.x * blockDim.x + threadIdx.x;
    if (i < B_ * L_) g_cbar[i] = 0.0f;
}

// ---------------- mma helpers ----------------
#define LDSM4(R0, R1, R2, R3, A) \
    asm volatile("ldmatrix.sync.aligned.m8n8.x4.shared.b16 {%0,%1,%2,%3}, [%4];" \
                 : "=r"(R0), "=r"(R1), "=r"(R2), "=r"(R3) : "r"(A))

#define MMAF16(D, A0, A1, A2, A3, B0, B1) \
    asm volatile("mma.sync.aligned.m16n8k16.row.col.f32.f16.f16.f32 " \
                 "{%0,%1,%2,%3},{%4,%5,%6,%7},{%8,%9},{%0,%1,%2,%3};" \
                 : "+f"(D[0]), "+f"(D[1]), "+f"(D[2]), "+f"(D[3]) \
                 : "r"(A0), "r"(A1), "r"(A2), "r"(A3), "r"(B0), "r"(B1))

__device__ __forceinline__ uint32_t pack_h2(__half a, __half b) {
    __half2 h = __halves2half2(a, b);
    return *(uint32_t*)&h;
}

// ---------------- fused convert + tensor-core GEMM + diagonal epilogue ----------------
// grid (4,4,8), block 320. Warps 0-7: MMA consumers. Warps 8-9: producers.
// Split: q = qhi + qlo (fp16), G ~= Qhi^T*Khi + Qlo^T*Khi (dropped Qhi^T*Klo ~ 2^-11 rel)
__global__ __launch_bounds__(NTHR, 1) void gemm_kernel(const float* __restrict__ Q,
                                                       const float* __restrict__ K) {
    extern __shared__ __align__(128) char sm[];
    const uint32_t smem_base = (uint32_t)__cvta_generic_to_shared(sm);

    const int b  = blockIdx.z;
    const int t0 = blockIdx.y * 128;
    const int u0 = blockIdx.x * 128;
    const float* Qb = Q + (size_t)b * L_ * D_;
    const float* Kb = K + (size_t)b * L_ * D_;

    const int tid  = threadIdx.x;
    const int lane = tid & 31;
    const int warp = tid >> 5;

    if (warp >= 8) {
        // ---------------- producer ----------------
        const int tl = (warp - 8) * 32 + lane;   // 0..63, handles t = tl and tl+64
        for (int fill = 0; fill < 65; ++fill) {
            if (fill < 64) {
                const int kt = fill;
                char* stg = sm + (kt & 1) * STAGE_B;
                float vq[2][16], vk[2][16];
                #pragma unroll
                for (int h = 0; h < 2; ++h) {
                    const float* sq = Qb + (size_t)(kt * 16) * D_ + t0 + tl + h * 64;
                    const float* sk = Kb + (size_t)(kt * 16) * D_ + u0 + tl + h * 64;
                    #pragma unroll
                    for (int l = 0; l < 16; ++l) {
                        vq[h][l] = sq[(size_t)l * D_];
                        vk[h][l] = sk[(size_t)l * D_];
                    }
                }
                #pragma unroll
                for (int h = 0; h < 2; ++h) {
                    int t = tl + h * 64;
                    uint32_t qhi[8], qlo[8], khi[8];
                    #pragma unroll
                    for (int i = 0; i < 8; ++i) {
                        float a = vq[h][2 * i], c = vq[h][2 * i + 1];
                        __half ha = __float2half(a), hc = __float2half(c);
                        qhi[i] = pack_h2(ha, hc);
                        qlo[i] = pack_h2(__float2half(a - __half2float(ha)),
                                         __float2half(c - __half2float(hc)));
                        float e = vk[h][2 * i], f = vk[h][2 * i + 1];
                        khi[i] = pack_h2(__float2half(e), __float2half(f));
                    }
                    char* dqh = stg + t * (PADB * 2);
                    char* dql = dqh + TILE_B;
                    char* dkh = dqh + 2 * TILE_B;
                    ((uint4*)dqh)[0] = make_uint4(qhi[0], qhi[1], qhi[2], qhi[3]);
                    ((uint4*)dqh)[1] = make_uint4(qhi[4], qhi[5], qhi[6], qhi[7]);
                    ((uint4*)dql)[0] = make_uint4(qlo[0], qlo[1], qlo[2], qlo[3]);
                    ((uint4*)dql)[1] = make_uint4(qlo[4], qlo[5], qlo[6], qlo[7]);
                    ((uint4*)dkh)[0] = make_uint4(khi[0], khi[1], khi[2], khi[3]);
                    ((uint4*)dkh)[1] = make_uint4(khi[4], khi[5], khi[6], khi[7]);
                }
            }
            __syncthreads();
        }
    } else {
        // ---------------- consumer ----------------
        const int wm = warp & 1;
        const int wn = warp >> 1;
        const int a_row = lane & 15;
        const int a_col = ((lane >> 4) & 1) * 8;
        const int b_row = ((lane >> 4) << 3) + (lane & 7);
        const int b_col = ((lane >> 3) & 1) * 8;

        float acc[4][4][4];
        #pragma unroll
        for (int i = 0; i < 4; ++i)
            #pragma unroll
            for (int j = 0; j < 4; ++j)
                #pragma unroll
                for (int k = 0; k < 4; ++k) acc[i][j][k] = 0.0f;

        __syncthreads();   // stage 0 ready

        for (int kt = 0; kt < 64; ++kt) {
            const uint32_t base = smem_base + (kt & 1) * STAGE_B;
            uint32_t ah[4][4], al[4][4], bh[2][4];
            #pragma unroll
            for (int mt = 0; mt < 4; ++mt) {
                uint32_t addr = base + ((wm * 64 + mt * 16 + a_row) * PADB + a_col) * 2;
                LDSM4(ah[mt][0], ah[mt][1], ah[mt][2], ah[mt][3], addr);
                LDSM4(al[mt][0], al[mt][1], al[mt][2], al[mt][3], addr + TILE_B);
            }
            #pragma unroll
            for (int ng = 0; ng < 2; ++ng) {
                uint32_t addr = base + 2 * TILE_B
                              + ((wn * 32 + ng * 16 + b_row) * PADB + b_col) * 2;
                LDSM4(bh[ng][0], bh[ng][1], bh[ng][2], bh[ng][3], addr);
            }
            #pragma unroll
            for (int mt = 0; mt < 4; ++mt)
                #pragma unroll
                for (int nt = 0; nt < 4; ++nt) {
                    int g = nt >> 1, h = (nt & 1) * 2;
                    MMAF16(acc[mt][nt], ah[mt][0], ah[mt][1], ah[mt][2], ah[mt][3],
                           bh[g][h], bh[g][h + 1]);
                    MMAF16(acc[mt][nt], al[mt][0], al[mt][1], al[mt][2], al[mt][3],
                           bh[g][h], bh[g][h + 1]);
                }
            __syncthreads();
        }

        // stage C in smem
        float* Cs = (float*)sm;
        const int cg = lane >> 2, ct = (lane & 3) * 2;
        #pragma unroll
        for (int mt = 0; mt < 4; ++mt)
            #pragma unroll
            for (int nt = 0; nt < 4; ++nt) {
                int m = wm * 64 + mt * 16 + cg;
                int n = wn * 32 + nt * 8 + ct;
                Cs[m * CS + n]           = acc[mt][nt][0];
                Cs[m * CS + n + 1]       = acc[mt][nt][1];
                Cs[(m + 8) * CS + n]     = acc[mt][nt][2];
                Cs[(m + 8) * CS + n + 1] = acc[mt][nt][3];
            }
    }
    __syncthreads();

    // diagonal reduce (255 threads)
    const float* Cs = (const float*)sm;
    if (tid < 255) {
        int dlt = tid - 127;
        int rlo = dlt > 0 ? dlt : 0;
        int rhi = dlt < 0 ? 127 + dlt : 127;
        float s = 0.0f;
        for (int rr = rlo; rr <= rhi; ++rr) s += Cs[rr * CS + (rr - dlt)];
        int mi = (t0 - u0 + dlt) & 1023;
        atomicAdd(&g_cbar[b * L_ + mi], s * (1.0f / (float)L_));
    }
}

// ---------------- spectrum: one warp per (b,k), phasor recurrence ----------------
__global__ __launch_bounds__(256) void spec_kernel() {
    int gw   = blockIdx.x * 8 + (threadIdx.x >> 5);
    int lane = threadIdx.x & 31;
    int b = gw & 7;
    int k = gw >> 3;
    const float* cb = g_cbar + b * L_;
    const float W = -6.283185307179586f / 1024.0f;
    float2 w, ws;
    __sincosf(W * (float)((k * lane) & 1023), &w.y, &w.x);
    __sincosf(W * (float)((k * 32) & 1023), &ws.y, &ws.x);
    float re = 0.0f, im = 0.0f;
    int m = lane;
    #pragma unroll 8
    for (int i = 0; i < 32; ++i) {
        float c = cb[m];
        re = fmaf(c, w.x, re);
        im = fmaf(c, w.y, im);
        float wx = w.x * ws.x - w.y * ws.y;
        w.y = w.x * ws.y + w.y * ws.x;
        w.x = wx;
        m += 32;
    }
    #pragma unroll
    for (int o = 16; o > 0; o >>= 1) {
        re += __shfl_xor_sync(0xffffffffu, re, o);
        im += __shfl_xor_sync(0xffffffffu, im, o);
    }
    if (lane == 0) g_spec[b * NK + k] = make_float2(re, im);
}

// ---------------- interpolation: one warp per (b, 4 j's), phasor recurrence ----------------
__global__ __launch_bounds__(256) void meanval_kernel() {
    int gw   = blockIdx.x * 8 + (threadIdx.x >> 5);   // 0..4095
    int lane = threadIdx.x & 31;
    int b  = gw & 7;
    int j0 = gw >> 3;                                  // 0..511
    const float2* sp = g_spec + b * NK;
    const float W = 6.283185307179586f / 2047.0f;

    float wx[4], wy[4], sx[4], sy[4], acc[4];
    #pragma unroll
    for (int jj = 0; jj < 4; ++jj) {
        int j = j0 + 512 * jj;
        if (j >= NJ) j = 0;   // dummy, discarded on write
        __sincosf(W * (float)(((lane + 1) * j) % NJ), &wy[jj], &wx[jj]);
        __sincosf(W * (float)((32 * j) % NJ), &sy[jj], &sx[jj]);
        acc[jj] = 0.0f;
    }
    #pragma unroll
    for (int i = 0; i < 16; ++i) {
        float2 s = sp[1 + lane + 32 * i];
        #pragma unroll
        for (int jj = 0; jj < 4; ++jj) {
            acc[jj] += s.x * wx[jj] - s.y * wy[jj];
            float t = wx[jj] * sx[jj] - wy[jj] * sy[jj];
            wy[jj]  = wx[jj] * sy[jj] + wy[jj] * sx[jj];
            wx[jj]  = t;
        }
    }
    #pragma unroll
    for (int o = 16; o > 0; o >>= 1)
        #pragma unroll
        for (int jj = 0; jj < 4; ++jj)
            acc[jj] += __shfl_xor_sync(0xffffffffu, acc[jj], o);
    if (lane == 0) {
        float c0 = sp[0].x;
        #pragma unroll
        for (int jj = 0; jj < 4; ++jj) {
            int j = j0 + 512 * jj;
            if (j < NJ) g_mean[b * NJ + j] = (2.0f * acc[jj] + c0) * (1.0f / (float)NJ);
        }
    }
}

// ---------------- top-20: per-warp local top-20, then warp-0 merge ----------------
__global__ __launch_bounds__(256) void topk_kernel() {
    int b = blockIdx.x;
    int tid = threadIdx.x;
    int lane = tid & 31;
    int warp = tid >> 5;
    __shared__ float cv[8 * TOPK];
    __shared__ int   ci[8 * TOPK];

    float v[8]; int gi[8];
    #pragma unroll
    for (int j = 0; j < 8; ++j) {
        int i = warp * 256 + j * 32 + lane;
        gi[j] = i;
        v[j] = (i < NJ) ? g_mean[b * NJ + i] : -FLT_MAX;
    }
    for (int r = 0; r < TOPK; ++r) {
        float best = -FLT_MAX; int bi = NJ;
        #pragma unroll
        for (int j = 0; j < 8; ++j)
            if (v[j] > best || (v[j] == best && gi[j] < bi)) { best = v[j]; bi = gi[j]; }
        #pragma unroll
        for (int o = 16; o > 0; o >>= 1) {
            float v2 = __shfl_xor_sync(0xffffffffu, best, o);
            int   i2 = __shfl_xor_sync(0xffffffffu, bi, o);
            if (v2 > best || (v2 == best && i2 < bi)) { best = v2; bi = i2; }
        }
        if ((bi & 31) == lane) {
            int j = (bi >> 5) & 7;
            if (gi[j] == bi) v[j] = -FLT_MAX;
        }
        if (lane == 0) { cv[warp * TOPK + r] = best; ci[warp * TOPK + r] = bi; }
    }
    __syncthreads();

    if (warp == 0) {
        float mv[5]; int mi[5];
        #pragma unroll
        for (int j = 0; j < 5; ++j) { mv[j] = cv[j * 32 + lane]; mi[j] = ci[j * 32 + lane]; }
        float topv[TOPK]; int topi[TOPK];
        for (int r = 0; r < TOPK; ++r) {
            float best = -FLT_MAX; int bi = NJ;
            #pragma unroll
            for (int j = 0; j < 5; ++j)
                if (mv[j] > best || (mv[j] == best && mi[j] < bi)) { best = mv[j]; bi = mi[j]; }
            #pragma unroll
            for (int o = 16; o > 0; o >>= 1) {
                float v2 = __shfl_xor_sync(0xffffffffu, best, o);
                int   i2 = __shfl_xor_sync(0xffffffffu, bi, o);
                if (v2 > best || (v2 == best && i2 < bi)) { best = v2; bi = i2; }
            }
            #pragma unroll
            for (int j = 0; j < 5; ++j)
                if (mv[j] == best && mi[j] == bi) mv[j] = -FLT_MAX;
            topv[r] = best; topi[r] = bi;
        }
        if (lane == 0) {
            float mx = topv[0];
            float e[TOPK]; float s = 0.0f;
            for (int k = 0; k < TOPK; ++k) { e[k] = expf(topv[k] - mx); s += e[k]; }
            float inv = 1.0f / s;
            for (int k = 0; k < TOPK; ++k) g_w[b * TOPK + k] = e[k] * inv;
            if (b == 0) for (int k = 0; k < TOPK; ++k) g_shift[k] = topi[k];
        }
    }
}

// ---------------- gather: out[b,l,d] = sum_k w[b,k] * V[b,(l+shift[k])&1023,d] ----------------
__global__ __launch_bounds__(256) void gather_kernel(const float* __restrict__ V,
                                                     float* __restrict__ out) {
    int b  = blockIdx.y;
    int d0 = blockIdx.x * 8;
    __shared__ float sv[L_ * 8];
    __shared__ float sw[TOPK];
    __shared__ int   ssh[TOPK];
    const float* Vb = V + (size_t)b * L_ * D_;
    for (int idx = threadIdx.x; idx < L_ * 8; idx += 256) {
        int row = idx >> 3, c = idx & 7;
        sv[idx] = Vb[(size_t)row * D_ + d0 + c];
    }
    if (threadIdx.x < TOPK) {
        sw[threadIdx.x]  = g_w[b * TOPK + threadIdx.x];
        ssh[threadIdx.x] = g_shift[threadIdx.x] & (L_ - 1);
    }
    __syncthreads();
    int d  = threadIdx.x & 7;
    int lb = threadIdx.x >> 3;
    float* ob = out + (size_t)b * L_ * D_ + d0 + d;
    for (int l = lb; l < L_; l += 32) {
        float acc = 0.0f;
        #pragma unroll
        for (int k = 0; k < TOPK; ++k) {
            int row = (l + ssh[k]) & (L_ - 1);
            acc = fmaf(sw[k], sv[(row << 3) + d], acc);
        }
        ob[(size_t)l * D_] = acc;
    }
}

// ---------------- launch ----------------
extern "C" void kernel_launch(void* const* d_in, const int* in_sizes, int n_in,
                              void* d_out, int out_size) {
    const float* q = (const float*)d_in[0];
    const float* k = (const float*)d_in[1];
    const float* v = (const float*)d_in[2];
    float* out = (float*)d_out;

    cudaFuncSetAttribute(gemm_kernel, cudaFuncAttributeMaxDynamicSharedMemorySize, GEMM_SMEM);

    init_kernel<<<32, 256>>>();
    gemm_kernel<<<dim3(4, 4, B_), NTHR, GEMM_SMEM>>>(q, k);
    spec_kernel<<<513, 256>>>();
    meanval_kernel<<<512, 256>>>();
    topk_kernel<<<B_, 256>>>();
    gather_kernel<<<dim3(D_ / 8, B_), 256>>>(v, out);
}